// round 5
// baseline (speedup 1.0000x reference)
#include <cuda_runtime.h>
#include <cuda_bf16.h>

// Problem constants (fixed by the dataset)
#define B    256
#define G    20000
#define NTF  1024
#define NPT  8     // nodes per TF
#define GPT  64    // genes per TF
#define EPS  1e-5f
#define SLOPE 0.01f

// Scratch: x transposed to [G, B] for coalesced gene-row gathers. 20.48 MB.
__device__ float g_xT[(size_t)G * B];

// ---------------------------------------------------------------------------
// Kernel 1: transpose x [B, G] -> xT [G, B].  G = 625 * 32 exactly.
// ---------------------------------------------------------------------------
__global__ void __launch_bounds__(256) transpose_kernel(const float* __restrict__ x) {
    __shared__ float tile[32][33];
    const int g0 = blockIdx.x * 32;
    const int b0 = blockIdx.y * 32;
    const int tx = threadIdx.x;      // 0..31
    const int ty = threadIdx.y;      // 0..7

#pragma unroll
    for (int i = 0; i < 32; i += 8)
        tile[ty + i][tx] = x[(size_t)(b0 + ty + i) * G + (g0 + tx)];
    __syncthreads();
#pragma unroll
    for (int i = 0; i < 32; i += 8)
        g_xT[(size_t)(g0 + ty + i) * B + (b0 + tx)] = tile[tx][ty + i];
}

// ---------------------------------------------------------------------------
// Kernel 2: fused encoder. One 256-thread block per TF (grid = 1024).
//   Thread = batch element. 8192 warps total -> ~55 warps/SM available;
//   low register count targets 6 blocks/SM (75% occ) to hide the random
//   L2-hit gene gathers. 8-gene prefetch batches for MLP.
//   layer1 -> BN1 -> LeakyReLU -> layer2 -> BN2 -> LeakyReLU -> out.
// ---------------------------------------------------------------------------
__global__ void __launch_bounds__(256, 6) fused_encoder_kernel(
    const float* __restrict__ w1,
    const int*   __restrict__ in_idx1,
    const float* __restrict__ w2,
    float*       __restrict__ out)
{
    const int tid  = threadIdx.x;     // = batch index b
    const int wrp  = tid >> 5;        // 0..7
    const int lane = tid & 31;
    const int t    = blockIdx.x;

    __shared__ __align__(16) float sw1t[NPT * GPT];  // transposed: [g*8 + j]
    __shared__ int   sg[GPT];                        // gene offsets * B
    __shared__ float sw2[NPT];
    __shared__ float rsum[8][NPT + 2];               // per-warp partials
    __shared__ float rsq [8][NPT + 2];
    __shared__ float smean[NPT], srstd[NPT];
    __shared__ float zmean, zrstd;

    // ---- Stage weights (transposed to [gene][node]) + gene indices -----------
#pragma unroll
    for (int i = tid; i < NPT * GPT; i += 256) {
        const int j = i >> 6;          // node
        const int g = i & 63;          // gene slot
        sw1t[g * NPT + j] = w1[t * (NPT * GPT) + i];
    }
    if (tid < GPT) sg[tid]  = in_idx1[t * (NPT * GPT) + tid] * B;
    if (tid < NPT) sw2[tid] = w2[t * NPT + tid];
    __syncthreads();

    // ---- Layer 1: acc[j] = sum_g w1t[g][j] * xT[gene_g][b] -------------------
    float acc[NPT];
#pragma unroll
    for (int j = 0; j < NPT; j++) acc[j] = 0.f;

#pragma unroll
    for (int g0 = 0; g0 < GPT; g0 += 8) {
        // batch 8 gathers first (MLP = 8)
        float xv[8];
#pragma unroll
        for (int u = 0; u < 8; u++)
            xv[u] = __ldg(&g_xT[sg[g0 + u] + tid]);
#pragma unroll
        for (int u = 0; u < 8; u++) {
            const float4 wa = *(const float4*)&sw1t[(g0 + u) * NPT];
            const float4 wb = *(const float4*)&sw1t[(g0 + u) * NPT + 4];
            acc[0] = fmaf(wa.x, xv[u], acc[0]);
            acc[1] = fmaf(wa.y, xv[u], acc[1]);
            acc[2] = fmaf(wa.z, xv[u], acc[2]);
            acc[3] = fmaf(wa.w, xv[u], acc[3]);
            acc[4] = fmaf(wb.x, xv[u], acc[4]);
            acc[5] = fmaf(wb.y, xv[u], acc[5]);
            acc[6] = fmaf(wb.z, xv[u], acc[6]);
            acc[7] = fmaf(wb.w, xv[u], acc[7]);
        }
    }

    // ---- BN1 stats: mean/var over batch (256 threads) per node ---------------
#pragma unroll
    for (int j = 0; j < NPT; j++) {
        float s  = acc[j];
        float s2 = acc[j] * acc[j];
#pragma unroll
        for (int o = 16; o > 0; o >>= 1) {
            s  += __shfl_xor_sync(0xffffffffu, s,  o);
            s2 += __shfl_xor_sync(0xffffffffu, s2, o);
        }
        if (lane == 0) { rsum[wrp][j] = s; rsq[wrp][j] = s2; }
    }
    __syncthreads();
    if (tid < NPT) {
        float s = 0.f, s2 = 0.f;
#pragma unroll
        for (int w = 0; w < 8; w++) { s += rsum[w][tid]; s2 += rsq[w][tid]; }
        const float m   = s * (1.f / B);
        const float var = s2 * (1.f / B) - m * m;
        smean[tid] = m;
        srstd[tid] = rsqrtf(var + EPS);
    }
    __syncthreads();

    // ---- BN1 + LeakyReLU + Layer 2 dot ---------------------------------------
    float z = 0.f;
#pragma unroll
    for (int j = 0; j < NPT; j++) {
        float v = (acc[j] - smean[j]) * srstd[j];
        v = (v > 0.f) ? v : SLOPE * v;
        z = fmaf(sw2[j], v, z);
    }

    // ---- BN2 stats over the 256 batch values ---------------------------------
    {
        float s = z, s2 = z * z;
#pragma unroll
        for (int o = 16; o > 0; o >>= 1) {
            s  += __shfl_xor_sync(0xffffffffu, s,  o);
            s2 += __shfl_xor_sync(0xffffffffu, s2, o);
        }
        if (lane == 0) { rsum[wrp][NPT] = s; rsq[wrp][NPT] = s2; }
    }
    __syncthreads();
    if (tid == 0) {
        float s = 0.f, s2 = 0.f;
#pragma unroll
        for (int w = 0; w < 8; w++) { s += rsum[w][NPT]; s2 += rsq[w][NPT]; }
        const float m   = s * (1.f / B);
        const float var = s2 * (1.f / B) - m * m;
        zmean = m;
        zrstd = rsqrtf(var + EPS);
    }
    __syncthreads();

    float v = (z - zmean) * zrstd;
    v = (v > 0.f) ? v : SLOPE * v;
    out[(size_t)tid * NTF + t] = v;   // out[b, t]
}

// ---------------------------------------------------------------------------
extern "C" void kernel_launch(void* const* d_in, const int* in_sizes, int n_in,
                              void* d_out, int out_size) {
    const float* x       = (const float*)d_in[0];
    const float* w1      = (const float*)d_in[1];
    const int*   in_idx1 = (const int*)  d_in[2];
    const float* w2      = (const float*)d_in[4];
    float*       out     = (float*)d_out;

    dim3 tb(32, 8);
    dim3 tg(G / 32, B / 32);           // 625 x 8, exact
    transpose_kernel<<<tg, tb>>>(x);
    fused_encoder_kernel<<<NTF, 256>>>(w1, in_idx1, w2, out);
}

// round 6
// speedup vs baseline: 1.0012x; 1.0012x over previous
#include <cuda_runtime.h>
#include <cuda_bf16.h>

// Problem constants (fixed by the dataset)
#define B    256
#define G    20000
#define NTF  1024
#define NPT  8     // nodes per TF
#define GPT  64    // genes per TF
#define EPS  1e-5f
#define SLOPE 0.01f

typedef unsigned long long u64;

// Packed fp32x2 FMA (Blackwell): d = a*b + d elementwise on 2 packed floats.
#define FMA2(d, a, b) asm("fma.rn.f32x2 %0, %1, %2, %0;" : "+l"(d) : "l"(a), "l"(b))
#define UNPACK2(lo, hi, v) asm("mov.b64 {%0, %1}, %2;" : "=f"(lo), "=f"(hi) : "l"(v))

// Scratch: x transposed to [G, B] for coalesced gene-row gathers. 20.48 MB.
__device__ float g_xT[(size_t)G * B];

// ---------------------------------------------------------------------------
// Kernel 1: transpose x [B, G] -> xT [G, B].  G = 625 * 32 exactly.
// ---------------------------------------------------------------------------
__global__ void __launch_bounds__(256) transpose_kernel(const float* __restrict__ x) {
    __shared__ float tile[32][33];
    const int g0 = blockIdx.x * 32;
    const int b0 = blockIdx.y * 32;
    const int tx = threadIdx.x;      // 0..31
    const int ty = threadIdx.y;      // 0..7

#pragma unroll
    for (int i = 0; i < 32; i += 8)
        tile[ty + i][tx] = x[(size_t)(b0 + ty + i) * G + (g0 + tx)];
    __syncthreads();
#pragma unroll
    for (int i = 0; i < 32; i += 8)
        g_xT[(size_t)(g0 + ty + i) * B + (b0 + tx)] = tile[tx][ty + i];
}

// ---------------------------------------------------------------------------
// Kernel 2: fused encoder. One 128-thread block per TF (grid = 1024).
//   Each thread owns 2 batch elements as ONE packed f32x2.
//   Inner loop: fma.rn.f32x2 against pre-duplicated {w,w} smem weights,
//   4-gene double-buffered gather prefetch. Regs capped at 56 (grid is the
//   occupancy limiter at ~6.9 blocks/SM, so the cap is free).
// ---------------------------------------------------------------------------
__global__ void __launch_bounds__(128, 9) fused_encoder_kernel(
    const float* __restrict__ w1,
    const int*   __restrict__ in_idx1,
    const float* __restrict__ w2,
    float*       __restrict__ out)
{
    const int tid  = threadIdx.x;     // 0..127
    const int wrp  = tid >> 5;        // 0..3
    const int lane = tid & 31;
    const int t    = blockIdx.x;

    __shared__ __align__(16) float2 sw1d[NPT * GPT];  // [g*8 + j] = {w, w}
    __shared__ int   sg[GPT];                         // gene offsets * B
    __shared__ float sw2[NPT];
    __shared__ float rsum[4][NPT + 2];                // per-warp partials
    __shared__ float rsq [4][NPT + 2];
    __shared__ float smean[NPT], srstd[NPT];
    __shared__ float zmean, zrstd;

    // ---- Stage duplicated weights + gene indices -----------------------------
#pragma unroll
    for (int i = tid; i < NPT * GPT; i += 128) {
        const int j = i >> 6;          // node
        const int g = i & 63;          // gene slot
        const float w = w1[t * (NPT * GPT) + i];
        sw1d[g * NPT + j] = make_float2(w, w);
    }
    if (tid < GPT) sg[tid]  = in_idx1[t * (NPT * GPT) + tid] * B;
    if (tid < NPT) sw2[tid] = w2[t * NPT + tid];
    __syncthreads();

    // ---- Layer 1: acc2[j] = packed pair over 2 batch elems -------------------
    u64 acc2[NPT];
#pragma unroll
    for (int j = 0; j < NPT; j++) acc2[j] = 0ull;

    const int boff = 2 * tid;

    // per-gene: 4 LDS.128 of duplicated weights + 8 FFMA2
#define GENE_FMA(gidx, xv)                                                     \
    {                                                                          \
        const ulonglong2 w01 = *(const ulonglong2*)&sw1d[(gidx) * NPT + 0];    \
        const ulonglong2 w23 = *(const ulonglong2*)&sw1d[(gidx) * NPT + 2];    \
        FMA2(acc2[0], w01.x, (xv)); FMA2(acc2[1], w01.y, (xv));                \
        FMA2(acc2[2], w23.x, (xv)); FMA2(acc2[3], w23.y, (xv));                \
        const ulonglong2 w45 = *(const ulonglong2*)&sw1d[(gidx) * NPT + 4];    \
        const ulonglong2 w67 = *(const ulonglong2*)&sw1d[(gidx) * NPT + 6];    \
        FMA2(acc2[4], w45.x, (xv)); FMA2(acc2[5], w45.y, (xv));                \
        FMA2(acc2[6], w67.x, (xv)); FMA2(acc2[7], w67.y, (xv));                \
    }

    u64 xa[4], xb[4];
#pragma unroll
    for (int u = 0; u < 4; u++)
        xa[u] = *(const u64*)&g_xT[sg[u] + boff];

#pragma unroll
    for (int g0 = 0; g0 < GPT; g0 += 8) {
        // prefetch genes g0+4 .. g0+7
#pragma unroll
        for (int u = 0; u < 4; u++)
            xb[u] = *(const u64*)&g_xT[sg[g0 + 4 + u] + boff];
        // compute genes g0 .. g0+3
#pragma unroll
        for (int u = 0; u < 4; u++) GENE_FMA(g0 + u, xa[u]);
        // prefetch genes g0+8 .. g0+11
        if (g0 + 8 < GPT) {
#pragma unroll
            for (int u = 0; u < 4; u++)
                xa[u] = *(const u64*)&g_xT[sg[g0 + 8 + u] + boff];
        }
        // compute genes g0+4 .. g0+7
#pragma unroll
        for (int u = 0; u < 4; u++) GENE_FMA(g0 + 4 + u, xb[u]);
    }

    // unpack accumulators
    float2 acc[NPT];
#pragma unroll
    for (int j = 0; j < NPT; j++) UNPACK2(acc[j].x, acc[j].y, acc2[j]);

    // ---- BN1 stats: sum over 256 batch elems (128 threads x 2) per node ------
#pragma unroll
    for (int j = 0; j < NPT; j++) {
        float s  = acc[j].x + acc[j].y;
        float s2 = acc[j].x * acc[j].x + acc[j].y * acc[j].y;
#pragma unroll
        for (int o = 16; o > 0; o >>= 1) {
            s  += __shfl_xor_sync(0xffffffffu, s,  o);
            s2 += __shfl_xor_sync(0xffffffffu, s2, o);
        }
        if (lane == 0) { rsum[wrp][j] = s; rsq[wrp][j] = s2; }
    }
    __syncthreads();
    if (tid < NPT) {
        float s = 0.f, s2 = 0.f;
#pragma unroll
        for (int w = 0; w < 4; w++) { s += rsum[w][tid]; s2 += rsq[w][tid]; }
        const float m   = s * (1.f / B);
        const float var = s2 * (1.f / B) - m * m;
        smean[tid] = m;
        srstd[tid] = rsqrtf(var + EPS);
    }
    __syncthreads();

    // ---- BN1 + LeakyReLU + Layer 2 dot ---------------------------------------
    float z0 = 0.f, z1 = 0.f;
#pragma unroll
    for (int j = 0; j < NPT; j++) {
        const float m = smean[j], r = srstd[j], w = sw2[j];
        float v0 = (acc[j].x - m) * r;  v0 = (v0 > 0.f) ? v0 : SLOPE * v0;
        float v1 = (acc[j].y - m) * r;  v1 = (v1 > 0.f) ? v1 : SLOPE * v1;
        z0 = fmaf(w, v0, z0);
        z1 = fmaf(w, v1, z1);
    }

    // ---- BN2 stats over 256 batch values -------------------------------------
    {
        float s = z0 + z1, s2 = z0 * z0 + z1 * z1;
#pragma unroll
        for (int o = 16; o > 0; o >>= 1) {
            s  += __shfl_xor_sync(0xffffffffu, s,  o);
            s2 += __shfl_xor_sync(0xffffffffu, s2, o);
        }
        if (lane == 0) { rsum[wrp][NPT] = s; rsq[wrp][NPT] = s2; }
    }
    __syncthreads();
    if (tid == 0) {
        float s = 0.f, s2 = 0.f;
#pragma unroll
        for (int w = 0; w < 4; w++) { s += rsum[w][NPT]; s2 += rsq[w][NPT]; }
        const float m   = s * (1.f / B);
        const float var = s2 * (1.f / B) - m * m;
        zmean = m;
        zrstd = rsqrtf(var + EPS);
    }
    __syncthreads();

    const float m = zmean, r = zrstd;
    float v0 = (z0 - m) * r;  v0 = (v0 > 0.f) ? v0 : SLOPE * v0;
    float v1 = (z1 - m) * r;  v1 = (v1 > 0.f) ? v1 : SLOPE * v1;
    out[(size_t)(boff)     * NTF + t] = v0;
    out[(size_t)(boff + 1) * NTF + t] = v1;
}

// ---------------------------------------------------------------------------
extern "C" void kernel_launch(void* const* d_in, const int* in_sizes, int n_in,
                              void* d_out, int out_size) {
    const float* x       = (const float*)d_in[0];
    const float* w1      = (const float*)d_in[1];
    const int*   in_idx1 = (const int*)  d_in[2];
    const float* w2      = (const float*)d_in[4];
    float*       out     = (float*)d_out;

    dim3 tb(32, 8);
    dim3 tg(G / 32, B / 32);           // 625 x 8, exact
    transpose_kernel<<<tg, tb>>>(x);
    fused_encoder_kernel<<<NTF, 128>>>(w1, in_idx1, w2, out);
}

// round 9
// speedup vs baseline: 1.0317x; 1.0305x over previous
#include <cuda_runtime.h>
#include <cuda_bf16.h>
#include <cstdint>

// Problem constants (fixed by the dataset)
#define B    256
#define G    20000
#define NTF  1024
#define NPT  8     // nodes per TF
#define GPT  64    // genes per TF
#define EPS  1e-5f
#define SLOPE 0.01f

#define CHUNK   16                 // genes per pipeline chunk
#define NCHUNK  (GPT / CHUNK)      // 4
#define CHUNK_BYTES (CHUNK * B * 4)  // 16 KB

// Scratch: x transposed to [G, B] for coalesced/bulk gene-row reads. 20.48 MB.
__device__ float g_xT[(size_t)G * B];

// ---------------------------------------------------------------------------
// Kernel 1: transpose x [B, G] -> xT [G, B].  G = 625 * 32 exactly.
// ---------------------------------------------------------------------------
__global__ void __launch_bounds__(256) transpose_kernel(const float* __restrict__ x) {
    __shared__ float tile[32][33];
    const int g0 = blockIdx.x * 32;
    const int b0 = blockIdx.y * 32;
    const int tx = threadIdx.x;      // 0..31
    const int ty = threadIdx.y;      // 0..7

#pragma unroll
    for (int i = 0; i < 32; i += 8)
        tile[ty + i][tx] = x[(size_t)(b0 + ty + i) * G + (g0 + tx)];
    __syncthreads();
#pragma unroll
    for (int i = 0; i < 32; i += 8)
        g_xT[(size_t)(g0 + ty + i) * B + (b0 + tx)] = tile[tx][ty + i];
}

// ---------------------------------------------------------------------------
// mbarrier helpers
// ---------------------------------------------------------------------------
__device__ __forceinline__ uint32_t smem_u32(const void* p) {
    uint32_t a;
    asm("{ .reg .u64 t; cvta.to.shared.u64 t, %1; cvt.u32.u64 %0, t; }" : "=r"(a) : "l"(p));
    return a;
}
__device__ __forceinline__ void mbar_init(uint32_t mbar, uint32_t cnt) {
    asm volatile("mbarrier.init.shared.b64 [%0], %1;" :: "r"(mbar), "r"(cnt) : "memory");
}
__device__ __forceinline__ void mbar_expect_tx(uint32_t mbar, uint32_t bytes) {
    asm volatile("mbarrier.arrive.expect_tx.shared.b64 _, [%0], %1;" :: "r"(mbar), "r"(bytes) : "memory");
}
__device__ __forceinline__ void mbar_wait(uint32_t mbar, uint32_t phase) {
    uint32_t done;
    asm volatile(
        "{\n\t.reg .pred p;\n\t"
        "mbarrier.try_wait.parity.acquire.cta.shared::cta.b64 p, [%1], %2;\n\t"
        "selp.b32 %0, 1, 0, p;\n\t}"
        : "=r"(done) : "r"(mbar), "r"(phase) : "memory");
    if (!done) {
        asm volatile(
            "{\n\t.reg .pred P1;\n\t"
            "WL_%=:\n\t"
            "mbarrier.try_wait.parity.acquire.cta.shared::cta.b64 P1, [%0], %1, 0x989680;\n\t"
            "@P1 bra.uni WD_%=;\n\t"
            "bra.uni WL_%=;\n\t"
            "WD_%=:\n\t}"
            :: "r"(mbar), "r"(phase) : "memory");
    }
}
// One-instruction bulk copy of `bytes` from global to shared (UBLKCP).
__device__ __forceinline__ void bulk_g2s(uint32_t dst_smem, const void* gsrc,
                                         uint32_t bytes, uint32_t mbar) {
    asm volatile(
        "cp.async.bulk.shared::cta.global.mbarrier::complete_tx::bytes [%0], [%1], %2, [%3];"
        :: "r"(dst_smem), "l"(gsrc), "r"(bytes), "r"(mbar) : "memory");
}

// ---------------------------------------------------------------------------
// Kernel 2: fused encoder. One 128-thread block per TF (grid = 1024).
//   Gene rows staged smem via cp.async.bulk (1 instr / 1KB row), 2-buffer
//   ring, 16 genes/chunk. Consumer path is pure smem: LDS.64 x + LDS.128
//   weights + scalar FFMA. Each thread owns 2 batch elements.
// ---------------------------------------------------------------------------
__global__ void __launch_bounds__(128, 6) fused_encoder_kernel(
    const float* __restrict__ w1,
    const int*   __restrict__ in_idx1,
    const float* __restrict__ w2,
    float*       __restrict__ out)
{
    const int tid  = threadIdx.x;     // 0..127
    const int wrp  = tid >> 5;        // 0..3
    const int lane = tid & 31;
    const int t    = blockIdx.x;

    __shared__ __align__(16) float xbuf[2][CHUNK][B];   // 32 KB ring
    __shared__ __align__(16) float sw1t[NPT * GPT];     // [g*8 + j]
    __shared__ int   sg[GPT];                           // gene element offsets (*B)
    __shared__ float sw2[NPT];
    __shared__ __align__(8) unsigned long long full[2]; // mbarriers
    __shared__ float rsum[4][NPT + 2];
    __shared__ float rsq [4][NPT + 2];
    __shared__ float smean[NPT], srstd[NPT];
    __shared__ float zmean, zrstd;

    const uint32_t mb0 = smem_u32(&full[0]);
    const uint32_t mb1 = smem_u32(&full[1]);
    const uint32_t xb0 = smem_u32(&xbuf[0][0][0]);
    const uint32_t xb1 = smem_u32(&xbuf[1][0][0]);

    // ---- Stage weights (transposed) + gene indices + init mbarriers ----------
#pragma unroll
    for (int i = tid; i < NPT * GPT; i += 128) {
        const int j = i >> 6;          // node
        const int g = i & 63;          // gene slot
        sw1t[g * NPT + j] = w1[t * (NPT * GPT) + i];
    }
    if (tid < GPT) sg[tid]  = in_idx1[t * (NPT * GPT) + tid] * B;
    if (tid < NPT) sw2[tid] = w2[t * NPT + tid];
    if (tid == 0) { mbar_init(mb0, 1); mbar_init(mb1, 1); }
    __syncthreads();
    if (tid == 0) {
        asm volatile("fence.proxy.async.shared::cta;" ::: "memory");
        // issue chunks 0 and 1
        mbar_expect_tx(mb0, CHUNK_BYTES);
#pragma unroll
        for (int u = 0; u < CHUNK; u++)
            bulk_g2s(xb0 + u * (B * 4), &g_xT[sg[u]], B * 4, mb0);
        mbar_expect_tx(mb1, CHUNK_BYTES);
#pragma unroll
        for (int u = 0; u < CHUNK; u++)
            bulk_g2s(xb1 + u * (B * 4), &g_xT[sg[CHUNK + u]], B * 4, mb1);
    }

    // ---- Layer 1 mainloop: consume chunks from smem --------------------------
    float2 acc[NPT];
#pragma unroll
    for (int j = 0; j < NPT; j++) acc[j] = make_float2(0.f, 0.f);

    const int boff = 2 * tid;

#pragma unroll
    for (int c = 0; c < NCHUNK; c++) {
        const int buf   = c & 1;
        const int phase = c >> 1;
        mbar_wait(buf ? mb1 : mb0, phase);

#pragma unroll
        for (int u = 0; u < CHUNK; u++) {
            const float2 xv = *(const float2*)&xbuf[buf][u][boff];
            const int gg = c * CHUNK + u;
            const float4 wa = *(const float4*)&sw1t[gg * NPT];
            const float4 wb = *(const float4*)&sw1t[gg * NPT + 4];
            acc[0].x = fmaf(wa.x, xv.x, acc[0].x); acc[0].y = fmaf(wa.x, xv.y, acc[0].y);
            acc[1].x = fmaf(wa.y, xv.x, acc[1].x); acc[1].y = fmaf(wa.y, xv.y, acc[1].y);
            acc[2].x = fmaf(wa.z, xv.x, acc[2].x); acc[2].y = fmaf(wa.z, xv.y, acc[2].y);
            acc[3].x = fmaf(wa.w, xv.x, acc[3].x); acc[3].y = fmaf(wa.w, xv.y, acc[3].y);
            acc[4].x = fmaf(wb.x, xv.x, acc[4].x); acc[4].y = fmaf(wb.x, xv.y, acc[4].y);
            acc[5].x = fmaf(wb.y, xv.x, acc[5].x); acc[5].y = fmaf(wb.y, xv.y, acc[5].y);
            acc[6].x = fmaf(wb.z, xv.x, acc[6].x); acc[6].y = fmaf(wb.z, xv.y, acc[6].y);
            acc[7].x = fmaf(wb.w, xv.x, acc[7].x); acc[7].y = fmaf(wb.w, xv.y, acc[7].y);
        }

        // refill this buffer with chunk c+2 once all threads are done with it
        if (c + 2 < NCHUNK) {
            __syncthreads();
            if (tid == 0) {
                const uint32_t mb = buf ? mb1 : mb0;
                const uint32_t xb = buf ? xb1 : xb0;
                mbar_expect_tx(mb, CHUNK_BYTES);
#pragma unroll
                for (int u = 0; u < CHUNK; u++)
                    bulk_g2s(xb + u * (B * 4), &g_xT[sg[(c + 2) * CHUNK + u]], B * 4, mb);
            }
        }
    }

    // ---- BN1 stats: sum over 256 batch elems (128 threads x 2) per node ------
#pragma unroll
    for (int j = 0; j < NPT; j++) {
        float s  = acc[j].x + acc[j].y;
        float s2 = acc[j].x * acc[j].x + acc[j].y * acc[j].y;
#pragma unroll
        for (int o = 16; o > 0; o >>= 1) {
            s  += __shfl_xor_sync(0xffffffffu, s,  o);
            s2 += __shfl_xor_sync(0xffffffffu, s2, o);
        }
        if (lane == 0) { rsum[wrp][j] = s; rsq[wrp][j] = s2; }
    }
    __syncthreads();
    if (tid < NPT) {
        float s = 0.f, s2 = 0.f;
#pragma unroll
        for (int w = 0; w < 4; w++) { s += rsum[w][tid]; s2 += rsq[w][tid]; }
        const float m   = s * (1.f / B);
        const float var = s2 * (1.f / B) - m * m;
        smean[tid] = m;
        srstd[tid] = rsqrtf(var + EPS);
    }
    __syncthreads();

    // ---- BN1 + LeakyReLU + Layer 2 dot ---------------------------------------
    float z0 = 0.f, z1 = 0.f;
#pragma unroll
    for (int j = 0; j < NPT; j++) {
        const float m = smean[j], r = srstd[j], w = sw2[j];
        float v0 = (acc[j].x - m) * r;  v0 = (v0 > 0.f) ? v0 : SLOPE * v0;
        float v1 = (acc[j].y - m) * r;  v1 = (v1 > 0.f) ? v1 : SLOPE * v1;
        z0 = fmaf(w, v0, z0);
        z1 = fmaf(w, v1, z1);
    }

    // ---- BN2 stats over 256 batch values -------------------------------------
    {
        float s = z0 + z1, s2 = z0 * z0 + z1 * z1;
#pragma unroll
        for (int o = 16; o > 0; o >>= 1) {
            s  += __shfl_xor_sync(0xffffffffu, s,  o);
            s2 += __shfl_xor_sync(0xffffffffu, s2, o);
        }
        if (lane == 0) { rsum[wrp][NPT] = s; rsq[wrp][NPT] = s2; }
    }
    __syncthreads();
    if (tid == 0) {
        float s = 0.f, s2 = 0.f;
#pragma unroll
        for (int w = 0; w < 4; w++) { s += rsum[w][NPT]; s2 += rsq[w][NPT]; }
        const float m   = s * (1.f / B);
        const float var = s2 * (1.f / B) - m * m;
        zmean = m;
        zrstd = rsqrtf(var + EPS);
    }
    __syncthreads();

    const float m = zmean, r = zrstd;
    float v0 = (z0 - m) * r;  v0 = (v0 > 0.f) ? v0 : SLOPE * v0;
    float v1 = (z1 - m) * r;  v1 = (v1 > 0.f) ? v1 : SLOPE * v1;
    out[(size_t)(boff)     * NTF + t] = v0;
    out[(size_t)(boff + 1) * NTF + t] = v1;
}

// ---------------------------------------------------------------------------
extern "C" void kernel_launch(void* const* d_in, const int* in_sizes, int n_in,
                              void* d_out, int out_size) {
    const float* x       = (const float*)d_in[0];
    const float* w1      = (const float*)d_in[1];
    const int*   in_idx1 = (const int*)  d_in[2];
    const float* w2      = (const float*)d_in[4];
    float*       out     = (float*)d_out;

    dim3 tb(32, 8);
    dim3 tg(G / 32, B / 32);           // 625 x 8, exact
    transpose_kernel<<<tg, tb>>>(x);
    fused_encoder_kernel<<<NTF, 128>>>(w1, in_idx1, w2, out);
}

// round 10
// speedup vs baseline: 1.1086x; 1.0746x over previous
#include <cuda_runtime.h>
#include <cuda_bf16.h>

// Problem constants (fixed by the dataset)
#define B    256
#define G    20000
#define NTF  1024
#define NPT  8     // nodes per TF
#define GPT  64    // genes per TF
#define EPS  1e-5f
#define SLOPE 0.01f

// Scratch: x transposed to [G, B] for coalesced gene-row gathers. 20.48 MB.
__device__ float g_xT[(size_t)G * B];

// ---------------------------------------------------------------------------
// Kernel 1: transpose x [B, G] -> xT [G, B].  G = 625 * 32 exactly.
// ---------------------------------------------------------------------------
__global__ void __launch_bounds__(256) transpose_kernel(const float* __restrict__ x) {
    __shared__ float tile[32][33];
    const int g0 = blockIdx.x * 32;
    const int b0 = blockIdx.y * 32;
    const int tx = threadIdx.x;      // 0..31
    const int ty = threadIdx.y;      // 0..7

#pragma unroll
    for (int i = 0; i < 32; i += 8)
        tile[ty + i][tx] = x[(size_t)(b0 + ty + i) * G + (g0 + tx)];
    __syncthreads();
#pragma unroll
    for (int i = 0; i < 32; i += 8)
        g_xT[(size_t)(g0 + ty + i) * B + (b0 + tx)] = tile[tx][ty + i];
}

// ---------------------------------------------------------------------------
// Kernel 2: fused encoder. One 256-thread block per TF (grid = 1024).
//   Gene-split: half-group h (128 threads) accumulates genes [32h, 32h+32)
//   for the SAME 2 batch elements per lane; partials combined via smem.
//   Doubles warps/SM vs the 128-thread version while HALVING each warp's
//   dependent gather chain (total LDG count unchanged).
//   layer1 -> BN1 -> LeakyReLU -> layer2 -> BN2 -> LeakyReLU -> out.
// ---------------------------------------------------------------------------
__global__ void __launch_bounds__(256, 5) fused_encoder_kernel(
    const float* __restrict__ w1,
    const int*   __restrict__ in_idx1,
    const float* __restrict__ w2,
    float*       __restrict__ out)
{
    const int tid  = threadIdx.x;     // 0..255
    const int h    = tid >> 7;        // gene-half: 0 or 1
    const int ht   = tid & 127;       // lane within half = batch-pair id
    const int wrp  = ht >> 5;         // 0..3 (warp within half)
    const int lane = tid & 31;
    const int t    = blockIdx.x;

    __shared__ __align__(16) float  sw1t[NPT * GPT];   // [g*8 + j]
    __shared__ int    sg[GPT];                         // gene offsets * B
    __shared__ float  sw2[NPT];
    __shared__ __align__(16) float2 pacc[128][NPT];    // half-1 partials (8 KB)
    __shared__ float  rsum[4][NPT + 2];                // per-warp partials (half 0)
    __shared__ float  rsq [4][NPT + 2];
    __shared__ float  smean[NPT], srstd[NPT];
    __shared__ float  zmean, zrstd;

    // ---- Stage weights (transposed to [gene][node]) + gene indices -----------
#pragma unroll
    for (int i = tid; i < NPT * GPT; i += 256) {
        const int j = i >> 6;          // node
        const int g = i & 63;          // gene slot
        sw1t[g * NPT + j] = w1[t * (NPT * GPT) + i];
    }
    if (tid < GPT) sg[tid]  = in_idx1[t * (NPT * GPT) + tid] * B;
    if (tid < NPT) sw2[tid] = w2[t * NPT + tid];
    __syncthreads();

    // ---- Layer 1: acc[j] over this half's 32 genes ---------------------------
    float2 acc[NPT];
#pragma unroll
    for (int j = 0; j < NPT; j++) acc[j] = make_float2(0.f, 0.f);

    const int boff = 2 * ht;
    const int gbase = h * (GPT / 2);   // 0 or 32

#pragma unroll
    for (int g0 = 0; g0 < GPT / 2; g0 += 4) {
        float2 xv[4];
#pragma unroll
        for (int u = 0; u < 4; u++)
            xv[u] = *(const float2*)&g_xT[sg[gbase + g0 + u] + boff];
#pragma unroll
        for (int u = 0; u < 4; u++) {
            const int gg = gbase + g0 + u;
            const float4 wa = *(const float4*)&sw1t[gg * NPT];
            const float4 wb = *(const float4*)&sw1t[gg * NPT + 4];
            acc[0].x = fmaf(wa.x, xv[u].x, acc[0].x); acc[0].y = fmaf(wa.x, xv[u].y, acc[0].y);
            acc[1].x = fmaf(wa.y, xv[u].x, acc[1].x); acc[1].y = fmaf(wa.y, xv[u].y, acc[1].y);
            acc[2].x = fmaf(wa.z, xv[u].x, acc[2].x); acc[2].y = fmaf(wa.z, xv[u].y, acc[2].y);
            acc[3].x = fmaf(wa.w, xv[u].x, acc[3].x); acc[3].y = fmaf(wa.w, xv[u].y, acc[3].y);
            acc[4].x = fmaf(wb.x, xv[u].x, acc[4].x); acc[4].y = fmaf(wb.x, xv[u].y, acc[4].y);
            acc[5].x = fmaf(wb.y, xv[u].x, acc[5].x); acc[5].y = fmaf(wb.y, xv[u].y, acc[5].y);
            acc[6].x = fmaf(wb.z, xv[u].x, acc[6].x); acc[6].y = fmaf(wb.z, xv[u].y, acc[6].y);
            acc[7].x = fmaf(wb.w, xv[u].x, acc[7].x); acc[7].y = fmaf(wb.w, xv[u].y, acc[7].y);
        }
    }

    // ---- Combine the two gene-halves -----------------------------------------
    if (h == 1) {
#pragma unroll
        for (int j = 0; j < NPT; j++) pacc[ht][j] = acc[j];
    }
    __syncthreads();
    if (h == 0) {
#pragma unroll
        for (int j = 0; j < NPT; j++) {
            const float2 p = pacc[ht][j];
            acc[j].x += p.x;
            acc[j].y += p.y;
        }
        // ---- BN1 stats: 256 batch elems (128 threads x 2) per node ----------
#pragma unroll
        for (int j = 0; j < NPT; j++) {
            float s  = acc[j].x + acc[j].y;
            float s2 = acc[j].x * acc[j].x + acc[j].y * acc[j].y;
#pragma unroll
            for (int o = 16; o > 0; o >>= 1) {
                s  += __shfl_xor_sync(0xffffffffu, s,  o);
                s2 += __shfl_xor_sync(0xffffffffu, s2, o);
            }
            if (lane == 0) { rsum[wrp][j] = s; rsq[wrp][j] = s2; }
        }
    }
    __syncthreads();
    if (tid < NPT) {
        float s = 0.f, s2 = 0.f;
#pragma unroll
        for (int w = 0; w < 4; w++) { s += rsum[w][tid]; s2 += rsq[w][tid]; }
        const float m   = s * (1.f / B);
        const float var = s2 * (1.f / B) - m * m;
        smean[tid] = m;
        srstd[tid] = rsqrtf(var + EPS);
    }
    __syncthreads();

    // ---- BN1 + LeakyReLU + Layer 2 dot + BN2 partials (half 0 only) ----------
    float z0 = 0.f, z1 = 0.f;
    if (h == 0) {
#pragma unroll
        for (int j = 0; j < NPT; j++) {
            const float m = smean[j], r = srstd[j], w = sw2[j];
            float v0 = (acc[j].x - m) * r;  v0 = (v0 > 0.f) ? v0 : SLOPE * v0;
            float v1 = (acc[j].y - m) * r;  v1 = (v1 > 0.f) ? v1 : SLOPE * v1;
            z0 = fmaf(w, v0, z0);
            z1 = fmaf(w, v1, z1);
        }
        float s = z0 + z1, s2 = z0 * z0 + z1 * z1;
#pragma unroll
        for (int o = 16; o > 0; o >>= 1) {
            s  += __shfl_xor_sync(0xffffffffu, s,  o);
            s2 += __shfl_xor_sync(0xffffffffu, s2, o);
        }
        if (lane == 0) { rsum[wrp][NPT] = s; rsq[wrp][NPT] = s2; }
    }
    __syncthreads();
    if (tid == 0) {
        float s = 0.f, s2 = 0.f;
#pragma unroll
        for (int w = 0; w < 4; w++) { s += rsum[w][NPT]; s2 += rsq[w][NPT]; }
        const float m   = s * (1.f / B);
        const float var = s2 * (1.f / B) - m * m;
        zmean = m;
        zrstd = rsqrtf(var + EPS);
    }
    __syncthreads();

    if (h == 0) {
        const float m = zmean, r = zrstd;
        float v0 = (z0 - m) * r;  v0 = (v0 > 0.f) ? v0 : SLOPE * v0;
        float v1 = (z1 - m) * r;  v1 = (v1 > 0.f) ? v1 : SLOPE * v1;
        out[(size_t)(boff)     * NTF + t] = v0;
        out[(size_t)(boff + 1) * NTF + t] = v1;
    }
}

// ---------------------------------------------------------------------------
extern "C" void kernel_launch(void* const* d_in, const int* in_sizes, int n_in,
                              void* d_out, int out_size) {
    const float* x       = (const float*)d_in[0];
    const float* w1      = (const float*)d_in[1];
    const int*   in_idx1 = (const int*)  d_in[2];
    const float* w2      = (const float*)d_in[4];
    float*       out     = (float*)d_out;

    dim3 tb(32, 8);
    dim3 tg(G / 32, B / 32);           // 625 x 8, exact
    transpose_kernel<<<tg, tb>>>(x);
    fused_encoder_kernel<<<NTF, 256>>>(w1, in_idx1, w2, out);
}

// round 12
// speedup vs baseline: 1.2912x; 1.1646x over previous
#include <cuda_runtime.h>
#include <cuda_bf16.h>

// Problem constants (fixed by the dataset)
#define B    256
#define G    20000
#define NTF  1024
#define NPT  8     // nodes per TF
#define GPT  64    // genes per TF
#define EPS  1e-5f
#define SLOPE 0.01f

// Scratch: x transposed to [G, B] for coalesced gene-row gathers. 20.48 MB.
__device__ float g_xT[(size_t)G * B];

// ---------------------------------------------------------------------------
// Kernel 1: transpose x [B, G] -> xT [G, B].  G = 625 * 32 exactly.
// ---------------------------------------------------------------------------
__global__ void __launch_bounds__(256) transpose_kernel(const float* __restrict__ x) {
    __shared__ float tile[32][33];
    const int g0 = blockIdx.x * 32;
    const int b0 = blockIdx.y * 32;
    const int tx = threadIdx.x;      // 0..31
    const int ty = threadIdx.y;      // 0..7

#pragma unroll
    for (int i = 0; i < 32; i += 8)
        tile[ty + i][tx] = x[(size_t)(b0 + ty + i) * G + (g0 + tx)];
    __syncthreads();
#pragma unroll
    for (int i = 0; i < 32; i += 8)
        g_xT[(size_t)(g0 + ty + i) * B + (b0 + tx)] = tile[tx][ty + i];
}

// ---------------------------------------------------------------------------
// Kernel 2: fused encoder. One 128-thread block per TF (grid = 1024).
//   Each thread owns 2 batch elements (float2). DEEP gather prefetch:
//   8-gene double buffer => up to 16 LDG.64 in flight per thread (MLP~16).
//   Occupancy is grid-limited (6.9 blocks/SM), so the extra prefetch
//   registers are free: reg budget 73 via __launch_bounds__(128, 7).
//   layer1 -> BN1 -> LeakyReLU -> layer2 -> BN2 -> LeakyReLU -> out.
// ---------------------------------------------------------------------------
__global__ void __launch_bounds__(128, 7) fused_encoder_kernel(
    const float* __restrict__ w1,
    const int*   __restrict__ in_idx1,
    const float* __restrict__ w2,
    float*       __restrict__ out)
{
    const int tid  = threadIdx.x;     // 0..127
    const int wrp  = tid >> 5;        // 0..3
    const int lane = tid & 31;
    const int t    = blockIdx.x;

    __shared__ __align__(16) float sw1t[NPT * GPT];  // transposed: [g*8 + j]
    __shared__ int   sg[GPT];                        // gene offsets * B
    __shared__ float sw2[NPT];
    __shared__ float rsum[4][NPT + 2];               // per-warp partials
    __shared__ float rsq [4][NPT + 2];
    __shared__ float smean[NPT], srstd[NPT];
    __shared__ float zmean, zrstd;

    // ---- Stage weights (transposed to [gene][node]) + gene indices -----------
#pragma unroll
    for (int i = tid; i < NPT * GPT; i += 128) {
        const int j = i >> 6;          // node
        const int g = i & 63;          // gene slot
        sw1t[g * NPT + j] = w1[t * (NPT * GPT) + i];
    }
    if (tid < GPT) sg[tid]  = in_idx1[t * (NPT * GPT) + tid] * B;
    if (tid < NPT) sw2[tid] = w2[t * NPT + tid];
    __syncthreads();

    // ---- Layer 1: acc[j] (float2 over 2 batch elems) -------------------------
    float2 acc[NPT];
#pragma unroll
    for (int j = 0; j < NPT; j++) acc[j] = make_float2(0.f, 0.f);

    const int boff = 2 * tid;

    // 8 genes worth of FMAs against buffered gathers
#define GENE8_FMA(gbase, xv)                                                   \
    {                                                                          \
        _Pragma("unroll")                                                      \
        for (int u = 0; u < 8; u++) {                                          \
            const float4 wa = *(const float4*)&sw1t[((gbase) + u) * NPT];      \
            const float4 wb = *(const float4*)&sw1t[((gbase) + u) * NPT + 4];  \
            acc[0].x = fmaf(wa.x, xv[u].x, acc[0].x);                          \
            acc[0].y = fmaf(wa.x, xv[u].y, acc[0].y);                          \
            acc[1].x = fmaf(wa.y, xv[u].x, acc[1].x);                          \
            acc[1].y = fmaf(wa.y, xv[u].y, acc[1].y);                          \
            acc[2].x = fmaf(wa.z, xv[u].x, acc[2].x);                          \
            acc[2].y = fmaf(wa.z, xv[u].y, acc[2].y);                          \
            acc[3].x = fmaf(wa.w, xv[u].x, acc[3].x);                          \
            acc[3].y = fmaf(wa.w, xv[u].y, acc[3].y);                          \
            acc[4].x = fmaf(wb.x, xv[u].x, acc[4].x);                          \
            acc[4].y = fmaf(wb.x, xv[u].y, acc[4].y);                          \
            acc[5].x = fmaf(wb.y, xv[u].x, acc[5].x);                          \
            acc[5].y = fmaf(wb.y, xv[u].y, acc[5].y);                          \
            acc[6].x = fmaf(wb.z, xv[u].x, acc[6].x);                          \
            acc[6].y = fmaf(wb.z, xv[u].y, acc[6].y);                          \
            acc[7].x = fmaf(wb.w, xv[u].x, acc[7].x);                          \
            acc[7].y = fmaf(wb.w, xv[u].y, acc[7].y);                          \
        }                                                                      \
    }

    float2 xa[8], xb[8];
    // prime: genes 0..7 and 8..15 in flight together (MLP ~16)
#pragma unroll
    for (int u = 0; u < 8; u++)
        xa[u] = *(const float2*)&g_xT[sg[u] + boff];
#pragma unroll
    for (int u = 0; u < 8; u++)
        xb[u] = *(const float2*)&g_xT[sg[8 + u] + boff];

#pragma unroll
    for (int g0 = 0; g0 < GPT; g0 += 16) {
        // consume genes g0..g0+7, then refill xa with g0+16..g0+23
        GENE8_FMA(g0, xa);
        if (g0 + 16 < GPT) {
#pragma unroll
            for (int u = 0; u < 8; u++)
                xa[u] = *(const float2*)&g_xT[sg[g0 + 16 + u] + boff];
        }
        // consume genes g0+8..g0+15, then refill xb with g0+24..g0+31
        GENE8_FMA(g0 + 8, xb);
        if (g0 + 24 < GPT) {
#pragma unroll
            for (int u = 0; u < 8; u++)
                xb[u] = *(const float2*)&g_xT[sg[g0 + 24 + u] + boff];
        }
    }

    // ---- BN1 stats: sum over 256 batch elems (128 threads x 2) per node ------
#pragma unroll
    for (int j = 0; j < NPT; j++) {
        float s  = acc[j].x + acc[j].y;
        float s2 = acc[j].x * acc[j].x + acc[j].y * acc[j].y;
#pragma unroll
        for (int o = 16; o > 0; o >>= 1) {
            s  += __shfl_xor_sync(0xffffffffu, s,  o);
            s2 += __shfl_xor_sync(0xffffffffu, s2, o);
        }
        if (lane == 0) { rsum[wrp][j] = s; rsq[wrp][j] = s2; }
    }
    __syncthreads();
    if (tid < NPT) {
        float s = 0.f, s2 = 0.f;
#pragma unroll
        for (int w = 0; w < 4; w++) { s += rsum[w][tid]; s2 += rsq[w][tid]; }
        const float m   = s * (1.f / B);
        const float var = s2 * (1.f / B) - m * m;
        smean[tid] = m;
        srstd[tid] = rsqrtf(var + EPS);
    }
    __syncthreads();

    // ---- BN1 + LeakyReLU + Layer 2 dot ---------------------------------------
    float z0 = 0.f, z1 = 0.f;
#pragma unroll
    for (int j = 0; j < NPT; j++) {
        const float m = smean[j], r = srstd[j], w = sw2[j];
        float v0 = (acc[j].x - m) * r;  v0 = (v0 > 0.f) ? v0 : SLOPE * v0;
        float v1 = (acc[j].y - m) * r;  v1 = (v1 > 0.f) ? v1 : SLOPE * v1;
        z0 = fmaf(w, v0, z0);
        z1 = fmaf(w, v1, z1);
    }

    // ---- BN2 stats over 256 batch values -------------------------------------
    {
        float s = z0 + z1, s2 = z0 * z0 + z1 * z1;
#pragma unroll
        for (int o = 16; o > 0; o >>= 1) {
            s  += __shfl_xor_sync(0xffffffffu, s,  o);
            s2 += __shfl_xor_sync(0xffffffffu, s2, o);
        }
        if (lane == 0) { rsum[wrp][NPT] = s; rsq[wrp][NPT] = s2; }
    }
    __syncthreads();
    if (tid == 0) {
        float s = 0.f, s2 = 0.f;
#pragma unroll
        for (int w = 0; w < 4; w++) { s += rsum[w][NPT]; s2 += rsq[w][NPT]; }
        const float m   = s * (1.f / B);
        const float var = s2 * (1.f / B) - m * m;
        zmean = m;
        zrstd = rsqrtf(var + EPS);
    }
    __syncthreads();

    const float m = zmean, r = zrstd;
    float v0 = (z0 - m) * r;  v0 = (v0 > 0.f) ? v0 : SLOPE * v0;
    float v1 = (z1 - m) * r;  v1 = (v1 > 0.f) ? v1 : SLOPE * v1;
    out[(size_t)(boff)     * NTF + t] = v0;
    out[(size_t)(boff + 1) * NTF + t] = v1;
}

// ---------------------------------------------------------------------------
extern "C" void kernel_launch(void* const* d_in, const int* in_sizes, int n_in,
                              void* d_out, int out_size) {
    const float* x       = (const float*)d_in[0];
    const float* w1      = (const float*)d_in[1];
    const int*   in_idx1 = (const int*)  d_in[2];
    const float* w2      = (const float*)d_in[4];
    float*       out     = (float*)d_out;

    dim3 tb(32, 8);
    dim3 tg(G / 32, B / 32);           // 625 x 8, exact
    transpose_kernel<<<tg, tb>>>(x);
    fused_encoder_kernel<<<NTF, 128>>>(w1, in_idx1, w2, out);
}